// round 16
// baseline (speedup 1.0000x reference)
#include <cuda_runtime.h>
#include <cuda_fp16.h>
#include <cstdint>
#include <math.h>

#define NDIN 25
#define XPAD 26                 // padded row stride in floats (even -> aligned float2)
#define NDP  128
#define NROWS (256*2048)
#define TILE_M 256
#define NTILES (NROWS/TILE_M)   // 2048
#define NTHREADS 512
#define GRID 148
#define XBYTES (TILE_M*XPAD*4)  // 26624 per buffer

// ---------------- SMEM layout (byte offsets) ----------------
#define OFF_X0    0        // 26624 B (x tile buffer 0, 104B row stride)
#define OFF_X1    26624    // 26624 B (x tile buffer 1)
#define OFF_STAT  53248    // 2048 B  (256 x float2 {mu,rstd})
#define OFF_W1F   55296    // 8192 B  [s2][jp8][t32] uint4 (paired j; k=25 row carries b1)
#define OFF_W2F   63488    // 32768 B [s8][jp8][t32] uint4 (paired j)
#define OFF_B2    96256    // 512
#define OFF_G     96768    // 128
#define OFF_BETA  96896    // 128
#define SMEM_TOTAL 97024

__device__ __forceinline__ uint32_t smem_u32(const void* p) {
    uint32_t a;
    asm("{ .reg .u64 t; cvta.to.shared.u64 t, %1; cvt.u32.u64 %0, t; }" : "=r"(a) : "l"(p));
    return a;
}

__device__ __forceinline__ void mma_f16(float* c, uint32_t a0, uint32_t a1, uint32_t a2,
                                        uint32_t a3, uint32_t b0, uint32_t b1) {
    asm volatile("mma.sync.aligned.m16n8k16.row.col.f32.f16.f16.f32 "
                 "{%0,%1,%2,%3}, {%4,%5,%6,%7}, {%8,%9}, {%0,%1,%2,%3};"
                 : "+f"(c[0]), "+f"(c[1]), "+f"(c[2]), "+f"(c[3])
                 : "r"(a0), "r"(a1), "r"(a2), "r"(a3), "r"(b0), "r"(b1));
}

__device__ __forceinline__ void cp4(uint32_t saddr, const void* g) {
    asm volatile("cp.async.ca.shared.global [%0], [%1], 4;" :: "r"(saddr), "l"(g));
}
#define CP_COMMIT() asm volatile("cp.async.commit_group;" ::: "memory")
#define CP_WAIT0()  asm volatile("cp.async.wait_group 0;" ::: "memory")

__device__ __forceinline__ uint32_t pk2h(float f_lo, float f_hi) {
    __half2 h = __floats2half2_rn(f_lo, f_hi);
    return *reinterpret_cast<uint32_t*>(&h);
}

// Branch-free GELU (A&S 7.1.25, |eps_erf| <= 2.5e-5)
__device__ __forceinline__ float gelu_f(float v) {
    float av = fabsf(v);
    float z = av * 0.70710678118654752440f;
    float t = __fdividef(1.0f, fmaf(0.47047f, z, 1.0f));
    float p = t * fmaf(fmaf(0.7478556f, t, -0.0958798f), t, 0.3480242f);
    float e = __expf(-z * z);
    float w = 0.5f * av;
    float base = fmaf(0.5f, v, w);
    return fmaf(-p * e, w, base);
}

// per-row async copy: 100B packed gmem row -> 104B-strided smem row.
// ALL transfers are 4B (both addresses only guaranteed 4B-aligned).
// 2 threads per row: even thread words 0..12, odd thread words 13..24.
__device__ __forceinline__ void copy_x_tile(uint32_t dstbase, const char* src_tile, int tid) {
    int row = tid >> 1;
    int half = tid & 1;
    const char* src = src_tile + row * (NDIN * 4) + half * 52;
    uint32_t dst = dstbase + row * (XPAD * 4) + half * 52;
    int nw = 13 - half;   // even: 13 words (0..12), odd: 12 words (13..24)
    #pragma unroll
    for (int k = 0; k < 13; k++)
        if (k < nw) cp4(dst + 4 * k, src + 4 * k);
}

__global__ __launch_bounds__(NTHREADS, 1)
void ip_mma_kernel(const float* __restrict__ x,
                   const float* __restrict__ ln_g,
                   const float* __restrict__ ln_b,
                   const float* __restrict__ w1,
                   const float* __restrict__ b1,
                   const float* __restrict__ w2,
                   const float* __restrict__ b2,
                   float* __restrict__ out) {
    extern __shared__ char smem[];
    const uint32_t sb = smem_u32(smem);
    const int tid = threadIdx.x;
    const int lane = tid & 31;
    const int wid = tid >> 5;

    float* b2s = reinterpret_cast<float*>(smem + OFF_B2);
    float* gs  = reinterpret_cast<float*>(smem + OFF_G);
    float* bs  = reinterpret_cast<float*>(smem + OFF_BETA);
    float2* st = reinterpret_cast<float2*>(smem + OFF_STAT);

    if (tid < 128) b2s[tid] = b2[tid];
    if (tid >= 128 && tid < 128 + NDIN) {
        gs[tid - 128] = ln_g[tid - 128];
        bs[tid - 128] = ln_b[tid - 128];
    }

    // ---- zero-fill both X buffers once (pad words stay finite forever) ----
    {
        uint32_t* xz = reinterpret_cast<uint32_t*>(smem + OFF_X0);
        for (int i = tid; i < (2 * XBYTES) / 4; i += NTHREADS) xz[i] = 0;
    }

    // ---- stage w1 fragments, paired-j uint4: [s2][jp8][t32]; k==25 row carries b1 ----
    uint4* w1f = reinterpret_cast<uint4*>(smem + OFF_W1F);
    for (int idx = tid; idx < 2 * 8 * 32; idx += NTHREADS) {
        int t = idx & 31, jp = (idx >> 5) & 7, s = idx >> 8;
        int n_e = 8 * (2 * jp)     + (t >> 2);
        int n_o = 8 * (2 * jp + 1) + (t >> 2);
        int k0 = 16 * s + 2 * (t & 3);
        int kk[4] = {k0, k0 + 1, k0 + 8, k0 + 9};
        float ve[4], vo[4];
        #pragma unroll
        for (int q = 0; q < 4; q++) {
            ve[q] = (kk[q] < NDIN) ? w1[kk[q] * NDP + n_e]
                                   : ((kk[q] == NDIN) ? b1[n_e] : 0.0f);
            vo[q] = (kk[q] < NDIN) ? w1[kk[q] * NDP + n_o]
                                   : ((kk[q] == NDIN) ? b1[n_o] : 0.0f);
        }
        uint4 val;
        val.x = pk2h(ve[0], ve[1]);
        val.y = pk2h(ve[2], ve[3]);
        val.z = pk2h(vo[0], vo[1]);
        val.w = pk2h(vo[2], vo[3]);
        w1f[(s * 8 + jp) * 32 + t] = val;
    }
    // ---- stage w2 fragments, paired-j uint4: [s8][jp8][t32] ----
    uint4* w2f = reinterpret_cast<uint4*>(smem + OFF_W2F);
    for (int idx = tid; idx < 8 * 8 * 32; idx += NTHREADS) {
        int t = idx & 31, jp = (idx >> 5) & 7, s = idx >> 8;
        int n_e = 8 * (2 * jp)     + (t >> 2);
        int n_o = 8 * (2 * jp + 1) + (t >> 2);
        int k0 = 16 * s + 2 * (t & 3);
        uint4 val;
        val.x = pk2h(w2[k0 * NDP + n_e],       w2[(k0 + 1) * NDP + n_e]);
        val.y = pk2h(w2[(k0 + 8) * NDP + n_e], w2[(k0 + 9) * NDP + n_e]);
        val.z = pk2h(w2[k0 * NDP + n_o],       w2[(k0 + 1) * NDP + n_o]);
        val.w = pk2h(w2[(k0 + 8) * NDP + n_o], w2[(k0 + 9) * NDP + n_o]);
        w2f[(s * 8 + jp) * 32 + t] = val;
    }
    __syncthreads();   // zero-fill + staging visible before first cp.async

    const int m0 = wid * 16;
    const int q2 = 2 * (lane & 3);
    const int rA = m0 + (lane >> 2);
    const int rB = rA + 8;

    // ---- preload per-thread gamma/beta (k==25 slot: gamma=0, beta=1 -> b1 fold) ----
    float garr[2][2][2], bearr[2][2][2];
    #pragma unroll
    for (int s = 0; s < 2; s++)
        #pragma unroll
        for (int h = 0; h < 2; h++)
            #pragma unroll
            for (int par = 0; par < 2; par++) {
                int k = 16 * s + 8 * h + q2 + par;
                garr[s][h][par]  = (k < NDIN) ? gs[k] : 0.0f;
                bearr[s][h][par] = (k < NDIN) ? bs[k] : ((k == NDIN) ? 1.0f : 0.0f);
            }

    // ---- prologue: prefetch first x tile ----
    copy_x_tile(sb + OFF_X0, reinterpret_cast<const char*>(x) + (size_t)blockIdx.x * TILE_M * NDIN * 4, tid);
    CP_COMMIT();

    int bufsel = 0;
    for (int t = blockIdx.x; t < NTILES; t += GRID) {
        CP_WAIT0();
        __syncthreads();

        const float* Xc = reinterpret_cast<const float*>(smem + OFF_X0 + bufsel * XBYTES);

        // ---- prefetch next tile into the other buffer ----
        {
            int tn = t + GRID;
            if (tn < NTILES)
                copy_x_tile(sb + OFF_X0 + (bufsel ^ 1) * XBYTES,
                            reinterpret_cast<const char*>(x) + (size_t)tn * TILE_M * NDIN * 4, tid);
            CP_COMMIT();
        }

        // ---- warp-local LN stats: 2 lanes per row ----
        {
            int row = m0 + (lane >> 1);
            int half = lane & 1;
            const float* xr = Xc + row * XPAD;
            float sum = 0.0f, ssq = 0.0f;
            int k0 = half * 13, kcnt = 13 - half;
            #pragma unroll
            for (int k = 0; k < 13; k++) {
                if (k < kcnt) {
                    float v = xr[k0 + k];
                    sum += v;
                    ssq = fmaf(v, v, ssq);
                }
            }
            sum += __shfl_xor_sync(0xffffffffu, sum, 1);
            ssq += __shfl_xor_sync(0xffffffffu, ssq, 1);
            float mu = sum * (1.0f / NDIN);
            float var = fmaf(-mu, mu, ssq * (1.0f / NDIN));
            float rstd = rsqrtf(fmaxf(var, 0.0f) + 1e-5f);
            if (half == 0) st[row] = make_float2(mu, rstd);
        }
        __syncwarp();

        // ---- build GEMM1 A-frags from padded x (aligned float2 reads) ----
        uint32_t ah[8];
        {
            float2 sA = st[rA], sB = st[rB];
            #pragma unroll
            for (int s = 0; s < 2; s++) {
                #pragma unroll
                for (int h = 0; h < 2; h++) {
                    int k0 = 16 * s + 8 * h + q2;   // even
                    float2 xa = *reinterpret_cast<const float2*>(Xc + rA * XPAD + k0);
                    float2 xb = *reinterpret_cast<const float2*>(Xc + rB * XPAD + k0);
                    float eA0 = fmaf((xa.x - sA.x) * sA.y, garr[s][h][0], bearr[s][h][0]);
                    float eA1 = fmaf((xa.y - sA.x) * sA.y, garr[s][h][1], bearr[s][h][1]);
                    float eB0 = fmaf((xb.x - sB.x) * sB.y, garr[s][h][0], bearr[s][h][0]);
                    float eB1 = fmaf((xb.y - sB.x) * sB.y, garr[s][h][1], bearr[s][h][1]);
                    int i = 4 * s + 2 * h;
                    ah[i + 0] = pk2h(eA0, eA1);
                    ah[i + 1] = pk2h(eB0, eB1);
                }
            }
        }

        // ---- GEMM1: paired-j, LDS.128 feeds 2 independent MMAs ----
        float acc[16][4];
        #pragma unroll
        for (int j = 0; j < 16; j++)
            #pragma unroll
            for (int r = 0; r < 4; r++) acc[j][r] = 0.0f;

        const uint4* f1 = reinterpret_cast<const uint4*>(smem + OFF_W1F);
        #pragma unroll
        for (int jp = 0; jp < 8; jp++) {
            #pragma unroll
            for (int s = 0; s < 2; s++) {
                uint4 b = f1[(s * 8 + jp) * 32 + lane];
                mma_f16(acc[2*jp],   ah[4*s], ah[4*s+1], ah[4*s+2], ah[4*s+3], b.x, b.y);
                mma_f16(acc[2*jp+1], ah[4*s], ah[4*s+1], ah[4*s+2], ah[4*s+3], b.z, b.w);
            }
        }

        // ---- GELU (b1 folded), pack hi-only A2 frags ----
        uint32_t a2[8][4];
        #pragma unroll
        for (int j = 0; j < 16; j++) {
            float g0 = gelu_f(acc[j][0]);
            float g1 = gelu_f(acc[j][1]);
            float g2 = gelu_f(acc[j][2]);
            float g3 = gelu_f(acc[j][3]);
            int s = j >> 1, h = (j & 1) * 2;
            a2[s][h + 0] = pk2h(g0, g1);
            a2[s][h + 1] = pk2h(g2, g3);
        }

        // ---- GEMM2: paired-j halves, acc2 seeded with b2 ----
        const uint4* f2 = reinterpret_cast<const uint4*>(smem + OFF_W2F);
        const size_t row0 = (size_t)t * TILE_M + rA;
        #pragma unroll
        for (int half = 0; half < 2; half++) {
            float acc2[8][4];
            #pragma unroll
            for (int j8 = 0; j8 < 8; j8++) {
                const float2 bb = *reinterpret_cast<const float2*>(b2s + 8 * (8 * half + j8) + q2);
                acc2[j8][0] = bb.x;
                acc2[j8][1] = bb.y;
                acc2[j8][2] = bb.x;
                acc2[j8][3] = bb.y;
            }

            #pragma unroll
            for (int jpl = 0; jpl < 4; jpl++) {
                int jp = 4 * half + jpl;
                #pragma unroll
                for (int s = 0; s < 8; s++) {
                    uint4 b = f2[(s * 8 + jp) * 32 + lane];
                    mma_f16(acc2[2*jpl],   a2[s][0], a2[s][1], a2[s][2], a2[s][3], b.x, b.y);
                    mma_f16(acc2[2*jpl+1], a2[s][0], a2[s][1], a2[s][2], a2[s][3], b.z, b.w);
                }
            }

            #pragma unroll
            for (int j8 = 0; j8 < 8; j8++) {
                int col = 8 * (8 * half + j8) + q2;
                float2 o0 = make_float2(acc2[j8][0], acc2[j8][1]);
                float2 o1 = make_float2(acc2[j8][2], acc2[j8][3]);
                *reinterpret_cast<float2*>(out + row0 * NDP + col) = o0;
                *reinterpret_cast<float2*>(out + (row0 + 8) * NDP + col) = o1;
            }
        }

        bufsel ^= 1;
    }
}

extern "C" void kernel_launch(void* const* d_in, const int* in_sizes, int n_in,
                              void* d_out, int out_size) {
    (void)in_sizes; (void)n_in; (void)out_size;
    const float* x    = (const float*)d_in[0];
    const float* ln_g = (const float*)d_in[1];
    const float* ln_b = (const float*)d_in[2];
    const float* w1   = (const float*)d_in[3];
    const float* b1   = (const float*)d_in[4];
    const float* w2   = (const float*)d_in[5];
    const float* b2   = (const float*)d_in[6];
    float* out = (float*)d_out;

    cudaFuncSetAttribute(ip_mma_kernel, cudaFuncAttributeMaxDynamicSharedMemorySize, SMEM_TOTAL);
    ip_mma_kernel<<<GRID, NTHREADS, SMEM_TOTAL>>>(x, ln_g, ln_b, w1, b1, w2, b2, out);
}